// round 2
// baseline (speedup 1.0000x reference)
#include <cuda_runtime.h>
#include <math.h>

#define S_TOT 65536
#define CDIM 128

// ---------------- scratch (static device globals; no runtime allocation) ----
__device__ float g_mean[S_TOT];
__device__ float g_rstd[S_TOT];
__device__ float g_qkv[768u * S_TOT];        // q[0:256] k[256:512] v[512:768] rows
__device__ float g_aout[8u * S_TOT * 32u];   // [bh][query][c] contiguous
__device__ float g_qpd[8*32*16];
__device__ float g_qph[8*32*64];
__device__ float g_qpw[8*32*64];
__device__ float g_kpd[8*32*16];
__device__ float g_kph[8*32*64];
__device__ float g_kpw[8*32*64];
__device__ int   g_idxD[8*4];
__device__ int   g_idxH[8*8];
__device__ int   g_idxW[8*8];
__device__ float g_kf[8*256*32];
__device__ float g_vf[8*256*32];

__device__ __forceinline__ float warp_sum(float v){
  #pragma unroll
  for (int o=16;o;o>>=1) v += __shfl_xor_sync(0xffffffffu, v, o);
  return v;
}

// ---------------- 1) LayerNorm stats per spatial location --------------------
__global__ void k_ln_stats(const float* __restrict__ x){
  int s = blockIdx.x*blockDim.x + threadIdx.x;
  float sum=0.f, sq=0.f;
  #pragma unroll 8
  for (int c=0;c<CDIM;c++){
    float v = x[(size_t)c*S_TOT + s];
    sum += v; sq += v*v;
  }
  float m = sum*(1.f/128.f);
  float var = sq*(1.f/128.f) - m*m;
  g_mean[s] = m;
  g_rstd[s] = 1.f/sqrtf(var + 1e-5f);
}

// ---------------- 2/12) tiled SGEMM, 64x64 tile, 256 thr, 4x4 per thread -----
// MODE 0: C(g_qkv)[768,S] = w_qkv[768,128] @ LN(x)[128,S]
// MODE 1: C(d_out)[128,S] = w_out[128,256] @ g_aout(256,S) + b_out
template<int KDIM, int MODE>
__global__ void __launch_bounds__(256) k_gemm(
    const float* __restrict__ A, const float* __restrict__ Bext,
    float* __restrict__ Cext, const float* __restrict__ gg,
    const float* __restrict__ bb, const float* __restrict__ bias)
{
  const float* B = (MODE==0) ? Bext : g_aout;
  float* C = (MODE==0) ? g_qkv : Cext;
  __shared__ float As[16][64];
  __shared__ float Bs[16][64];
  int t = threadIdx.x;
  int m0 = blockIdx.y*64, n0 = blockIdx.x*64;
  int tx = t & 3,  ty = t >> 2;    // A loader: k-quad, m-row
  int tn = t & 63, tk = t >> 6;    // B loader: col, k-quad-group
  int tx2 = t & 15, ty2 = t >> 4;  // compute: n-sub, m-sub
  float acc[4][4];
  #pragma unroll
  for (int i=0;i<4;i++)
    #pragma unroll
    for (int j=0;j<4;j++) acc[i][j]=0.f;

  float mval=0.f, rval=0.f;
  if (MODE==0){ mval = g_mean[n0+tn]; rval = g_rstd[n0+tn]; }

  for (int k0 = 0; k0 < KDIM; k0 += 16){
    __syncthreads();
    float4 a4 = *(const float4*)(A + (size_t)(m0+ty)*KDIM + k0 + tx*4);
    As[tx*4+0][ty]=a4.x; As[tx*4+1][ty]=a4.y; As[tx*4+2][ty]=a4.z; As[tx*4+3][ty]=a4.w;
    #pragma unroll
    for (int u=0;u<4;u++){
      int k = k0 + tk*4 + u;
      float v = B[(size_t)k*S_TOT + n0 + tn];
      if (MODE==0) v = (v - mval)*rval*gg[k] + bb[k];
      Bs[tk*4+u][tn] = v;
    }
    __syncthreads();
    #pragma unroll
    for (int kk=0;kk<16;kk++){
      float4 av = *(const float4*)&As[kk][ty2*4];
      float4 bv = *(const float4*)&Bs[kk][tx2*4];
      float aa[4]={av.x,av.y,av.z,av.w};
      float bcol[4]={bv.x,bv.y,bv.z,bv.w};
      #pragma unroll
      for (int i=0;i<4;i++)
        #pragma unroll
        for (int j=0;j<4;j++) acc[i][j] += aa[i]*bcol[j];
    }
  }
  #pragma unroll
  for (int i=0;i<4;i++){
    int m = m0 + ty2*4 + i;
    float bo = (MODE==1) ? bias[m] : 0.f;
    float4 o;
    o.x = acc[i][0]+bo; o.y = acc[i][1]+bo; o.z = acc[i][2]+bo; o.w = acc[i][3]+bo;
    *(float4*)(C + (size_t)m*S_TOT + n0 + tx2*4) = o;
  }
}

// ---------------- 3) L2-normalize q,k in place over 32 channels --------------
__global__ void k_qknorm(){
  int idx = blockIdx.x*256 + threadIdx.x;      // 8 * 65536 threads
  int bh = idx >> 16, s = idx & 65535;
  float* qb = g_qkv + (size_t)(bh*32)*S_TOT + s;
  float* kb = g_qkv + (size_t)(256 + bh*32)*S_TOT + s;
  float qv[32], kv[32];
  float sq=0.f, sk=0.f;
  #pragma unroll
  for (int c=0;c<32;c++){
    qv[c]=qb[(size_t)c*S_TOT]; sq+=qv[c]*qv[c];
    kv[c]=kb[(size_t)c*S_TOT]; sk+=kv[c]*kv[c];
  }
  float qs  = 1.f/fmaxf(sqrtf(sq), 1e-12f);
  float ksc = 1.f/fmaxf(sqrtf(sk), 1e-12f);
  #pragma unroll
  for (int c=0;c<32;c++){
    qb[(size_t)c*S_TOT]=qv[c]*qs;
    kb[(size_t)c*S_TOT]=kv[c]*ksc;
  }
}

// ---------------- 4) probes: q (d,h,w) + k (d) -------------------------------
// s = m*4096 + i2*256 + t  =>  d=m, h=i2*4+(t>>6), w=t&63
__global__ void k_probes(){
  int bh = blockIdx.x >> 5, c = blockIdx.x & 31;
  int t = threadIdx.x, lane = t & 31;
  const float* qp = g_qkv + (size_t)(bh*32+c)*S_TOT;
  const float* kp = g_qkv + (size_t)(256+bh*32+c)*S_TOT;
  __shared__ float sqd[16], skd[16], sqh[64], sqw[64];
  if (t<64){ sqh[t]=0.f; sqw[t]=0.f; }
  if (t<16){ sqd[t]=0.f; skd[t]=0.f; }
  __syncthreads();
  float qW = 0.f;
  float qH[16];
  #pragma unroll
  for (int i=0;i<16;i++) qH[i]=0.f;
  #pragma unroll 1
  for (int m=0;m<16;m++){
    float qD=0.f, kD=0.f;
    #pragma unroll
    for (int i2=0;i2<16;i2++){
      int s = m*4096 + i2*256 + t;
      float qv = fabsf(qp[s]);
      float kv = fabsf(kp[s]);
      qD += qv; kD += kv; qW += qv; qH[i2] += qv;
    }
    qD = warp_sum(qD); kD = warp_sum(kD);
    if (lane==0){ atomicAdd(&sqd[m], qD); atomicAdd(&skd[m], kD); }
  }
  int hb = t >> 6;   // uniform within a warp
  #pragma unroll
  for (int i2=0;i2<16;i2++){
    float v = warp_sum(qH[i2]);
    if (lane==0) atomicAdd(&sqh[i2*4 + hb], v);
  }
  atomicAdd(&sqw[t & 63], qW);
  __syncthreads();
  if (t<16){ g_qpd[(bh*32+c)*16 + t] = sqd[t]; g_kpd[(bh*32+c)*16 + t] = skd[t]; }
  if (t<64){ g_qph[(bh*32+c)*64 + t] = sqh[t]; g_qpw[(bh*32+c)*64 + t] = sqw[t]; }
}

// ---------------- 5/7/9) score + top-k select (ties -> lowest index) ---------
template<int STAGE>
__global__ void k_score_topk(){
  int bh = blockIdx.x, lane = threadIdx.x;
  const int n  = (STAGE==0)?16:64;
  const int ks = (STAGE==0)?4:8;
  const float* qp = (STAGE==0)?g_qpd:((STAGE==1)?g_qph:g_qpw);
  const float* kp = (STAGE==0)?g_kpd:((STAGE==1)?g_kph:g_kpw);
  int* io = (STAGE==0)?g_idxD:((STAGE==1)?g_idxH:g_idxW);
  __shared__ float sc[64];
  for (int d=0; d<n; d++){
    float v = qp[(bh*32+lane)*n + d] * kp[(bh*32+lane)*n + d];
    v = warp_sum(v);
    if (lane==0) sc[d] = v;
  }
  __syncwarp();
  if (lane==0){
    unsigned long long used = 0ull;
    for (int r=0;r<ks;r++){
      float best=-3.4e38f; int bi=0;
      for (int d=0; d<n; d++){
        if (!((used>>d)&1ull) && sc[d] > best){ best=sc[d]; bi=d; }
      }
      used |= 1ull<<bi;
      io[bh*ks + r] = bi;
    }
  }
}

// ---------------- 6) k probe over h for d in idxD ----------------------------
__global__ void k_kprobe_h(){
  int bh = blockIdx.x>>5, c = blockIdx.x&31;
  int t = threadIdx.x, lane = t&31;
  const float* kp = g_qkv + (size_t)(256+bh*32+c)*S_TOT;
  __shared__ float sh[64];
  __shared__ int sd[4];
  if (t<64) sh[t]=0.f;
  if (t<4)  sd[t]=g_idxD[bh*4+t];
  __syncthreads();
  float acc[16];
  #pragma unroll
  for (int i=0;i<16;i++) acc[i]=0.f;
  #pragma unroll 1
  for (int di=0; di<4; di++){
    int d = sd[di];
    #pragma unroll
    for (int i2=0;i2<16;i2++){
      int s = d*4096 + i2*256 + t;
      acc[i2] += fabsf(kp[s]);
    }
  }
  int hb = t>>6;
  #pragma unroll
  for (int i2=0;i2<16;i2++){
    float v = warp_sum(acc[i2]);
    if (lane==0) atomicAdd(&sh[i2*4+hb], v);
  }
  __syncthreads();
  if (t<64) g_kph[(bh*32+c)*64+t] = sh[t];
}

// ---------------- 8) k probe over w for d in idxD, h in idxH -----------------
__global__ void k_kprobe_w(){
  int bh = blockIdx.x>>5, c = blockIdx.x&31;
  int t = threadIdx.x;
  const float* kp = g_qkv + (size_t)(256+bh*32+c)*S_TOT;
  __shared__ float sw[64];
  __shared__ int sd[4], shh[8];
  if (t<64) sw[t]=0.f;
  if (t<4)  sd[t]=g_idxD[bh*4+t];
  if (t<8)  shh[t]=g_idxH[bh*8+t];
  __syncthreads();
  float acc = 0.f;
  int r = t>>6, w = t&63;
  #pragma unroll
  for (int it=0; it<8; it++){
    int combo = r + it*4;            // covers 0..31 across threads
    int di = combo>>3, hi = combo&7;
    int s = sd[di]*4096 + shh[hi]*64 + w;
    acc += fabsf(kp[s]);
  }
  atomicAdd(&sw[w], acc);
  __syncthreads();
  if (t<64) g_kpw[(bh*32+c)*64+t] = sw[t];
}

// ---------------- 10) gather pruned K/V: [bh][j][c], j = di*64+hi*8+wi -------
__global__ void k_gather(){
  int bh = blockIdx.y;
  int t = threadIdx.x;
  int j = blockIdx.x*8 + (t>>5);
  int c = t & 31;
  int di = j>>6, hi = (j>>3)&7, wi = j&7;
  int s = g_idxD[bh*4+di]*4096 + g_idxH[bh*8+hi]*64 + g_idxW[bh*8+wi];
  g_kf[(bh*256+j)*32 + c] = g_qkv[(size_t)(256+bh*32+c)*S_TOT + s];
  g_vf[(bh*256+j)*32 + c] = g_qkv[(size_t)(512+bh*32+c)*S_TOT + s];
}

// ---------------- 11) attention: 1 query/thread, K/V in smem -----------------
// sim in [-1,1] (unit vectors) -> softmax without max subtraction is exact.
__global__ void __launch_bounds__(256) k_attn(){
  extern __shared__ float smem[];
  float* sk = smem;            // 256*32
  float* sv = smem + 8192;     // 256*32
  int bh = blockIdx.y, t = threadIdx.x;
  const float4* kf4 = (const float4*)(g_kf + (size_t)bh*8192);
  const float4* vf4 = (const float4*)(g_vf + (size_t)bh*8192);
  float4* sk4 = (float4*)sk; float4* sv4 = (float4*)sv;
  #pragma unroll
  for (int i=0;i<8;i++){
    sk4[t + i*256] = kf4[t + i*256];
    sv4[t + i*256] = vf4[t + i*256];
  }
  __syncthreads();
  int s = blockIdx.x*256 + t;
  const float* qb = g_qkv + (size_t)(bh*32)*S_TOT + s;
  float q[32];
  #pragma unroll
  for (int c=0;c<32;c++) q[c] = qb[(size_t)c*S_TOT];
  float out[32];
  #pragma unroll
  for (int c=0;c<32;c++) out[c]=0.f;
  float l = 0.f;
  #pragma unroll 2
  for (int j=0;j<256;j++){
    const float4* kk = (const float4*)(sk + j*32);
    float sim = 0.f;
    #pragma unroll
    for (int u=0;u<8;u++){
      float4 kv = kk[u];
      sim += q[u*4+0]*kv.x + q[u*4+1]*kv.y + q[u*4+2]*kv.z + q[u*4+3]*kv.w;
    }
    float p = __expf(sim);
    l += p;
    const float4* vv = (const float4*)(sv + j*32);
    #pragma unroll
    for (int u=0;u<8;u++){
      float4 vl = vv[u];
      out[u*4+0] += p*vl.x; out[u*4+1] += p*vl.y;
      out[u*4+2] += p*vl.z; out[u*4+3] += p*vl.w;
    }
  }
  float inv = 1.f/l;
  // contiguous [bh][query][c] layout == reference's raw reshape
  float4* ob = (float4*)(g_aout + ((size_t)bh*S_TOT + (size_t)s)*32u);
  #pragma unroll
  for (int u=0;u<8;u++){
    float4 o;
    o.x=out[u*4+0]*inv; o.y=out[u*4+1]*inv; o.z=out[u*4+2]*inv; o.w=out[u*4+3]*inv;
    ob[u] = o;
  }
}

// ---------------- host ------------------------------------------------------
extern "C" void kernel_launch(void* const* d_in, const int* in_sizes, int n_in,
                              void* d_out, int out_size) {
  (void)in_sizes; (void)n_in; (void)out_size;
  const float* x     = (const float*)d_in[0];
  const float* g     = (const float*)d_in[1];
  const float* b     = (const float*)d_in[2];
  const float* wqkv  = (const float*)d_in[3];
  const float* wout  = (const float*)d_in[4];
  const float* bout  = (const float*)d_in[5];
  float* out = (float*)d_out;

  k_ln_stats<<<S_TOT/256, 256>>>(x);
  k_gemm<128,0><<<dim3(S_TOT/64, 768/64), 256>>>(wqkv, x, nullptr, g, b, nullptr);
  k_qknorm<<<(8*S_TOT)/256, 256>>>();
  k_probes<<<256, 256>>>();
  k_score_topk<0><<<8, 32>>>();
  k_kprobe_h<<<256, 256>>>();
  k_score_topk<1><<<8, 32>>>();
  k_kprobe_w<<<256, 256>>>();
  k_score_topk<2><<<8, 32>>>();
  k_gather<<<dim3(32, 8), 256>>>();
  cudaFuncSetAttribute((const void*)k_attn,
                       cudaFuncAttributeMaxDynamicSharedMemorySize, 65536);
  k_attn<<<dim3(S_TOT/256, 8), 256, 65536>>>();
  k_gemm<256,1><<<dim3(S_TOT/64, 128/64), 256>>>(wout, nullptr, out, nullptr, nullptr, bout);
}

// round 3
// speedup vs baseline: 1.3386x; 1.3386x over previous
#include <cuda_runtime.h>
#include <math.h>

#define S_TOT 65536
#define CDIM 128
typedef unsigned long long ull;

// ---------------- scratch ----------------------------------------------------
__device__ float g_mean[S_TOT];
__device__ float g_rstd[S_TOT];
__device__ float g_qkv[768u * S_TOT];        // q[0:256] k[256:512] v[512:768]
__device__ float g_aout[8u * S_TOT * 32u];   // [bh][query][c]
__device__ float g_qpd[8*32*16];
__device__ float g_qph[8*32*64];
__device__ float g_qpw[8*32*64];
__device__ float g_kpd[8*32*16];
__device__ float g_kph[8*32*64];
__device__ float g_kpw[8*32*64];
__device__ int   g_idxD[8*4];
__device__ int   g_idxH[8*8];
__device__ int   g_idxW[8*8];
__device__ float g_kf[8*256*32];
__device__ float g_vf[8*256*32];

// ---------------- f32x2 helpers ----------------------------------------------
__device__ __forceinline__ ull ffma2(ull a, ull b, ull c){
  ull d; asm("fma.rn.f32x2 %0, %1, %2, %3;" : "=l"(d) : "l"(a), "l"(b), "l"(c)); return d;
}
__device__ __forceinline__ ull fmul2(ull a, ull b){
  ull d; asm("mul.rn.f32x2 %0, %1, %2;" : "=l"(d) : "l"(a), "l"(b)); return d;
}
__device__ __forceinline__ ull fadd2(ull a, ull b){
  ull d; asm("add.rn.f32x2 %0, %1, %2;" : "=l"(d) : "l"(a), "l"(b)); return d;
}
__device__ __forceinline__ ull dup2(float x){
  unsigned r = __float_as_uint(x);
  ull d; asm("mov.b64 %0, {%1, %2};" : "=l"(d) : "r"(r), "r"(r)); return d;
}
__device__ __forceinline__ ull pack2(float x, float y){
  ull d; asm("mov.b64 %0, {%1, %2};" : "=l"(d) : "r"(__float_as_uint(x)), "r"(__float_as_uint(y))); return d;
}
__device__ __forceinline__ float2 unpack2(ull v){
  unsigned lo, hi; asm("mov.b64 {%0, %1}, %2;" : "=r"(lo), "=r"(hi) : "l"(v));
  return make_float2(__uint_as_float(lo), __uint_as_float(hi));
}

__device__ __forceinline__ float warp_sum(float v){
  #pragma unroll
  for (int o=16;o;o>>=1) v += __shfl_xor_sync(0xffffffffu, v, o);
  return v;
}

// ---------------- 1) LayerNorm stats -----------------------------------------
__global__ void k_ln_stats(const float* __restrict__ x){
  int s = blockIdx.x*blockDim.x + threadIdx.x;
  float sum=0.f, sq=0.f;
  #pragma unroll 8
  for (int c=0;c<CDIM;c++){
    float v = x[(size_t)c*S_TOT + s];
    sum += v; sq += v*v;
  }
  float m = sum*(1.f/128.f);
  float var = sq*(1.f/128.f) - m*m;
  g_mean[s] = m;
  g_rstd[s] = 1.f/sqrtf(var + 1e-5f);
}

// ---------------- 2/12) SGEMM: 128x256 tile, 256 thr, 8x16/thread, f32x2 -----
// MODE 0: g_qkv[768,S] = w_qkv[768,128] @ LN(x)[128,S]; q,k rows l2-normalized
// MODE 1: Cx[128,S]    = w_out[128,256] @ g_aout(256,S) + bias
template<int KDIM, int MODE>
__global__ void __launch_bounds__(256) k_gemm(
    const float* __restrict__ A, const float* __restrict__ Bx,
    float* __restrict__ Cx, const float* __restrict__ gg,
    const float* __restrict__ bb, const float* __restrict__ bias)
{
  const float* B = (MODE==0) ? Bx : g_aout;
  float* C = (MODE==0) ? g_qkv : Cx;
  __shared__ __align__(16) float As[2][8][128];
  __shared__ __align__(16) float Bs[2][8][256];
  __shared__ __align__(16) float NormS[16][256];
  int t = threadIdx.x;
  int m0 = blockIdx.y*128, n0 = blockIdx.x*256;
  int tx = t & 15, ty = t >> 4;

  int lar = t >> 1, lak = (t & 1) * 4;     // A loader: row, k-quad
  int lbk = t >> 5, lbc = (t & 31) * 4;    // B loader: k-row, col base

  float4 mean4[2], rstd4[2];
  if (MODE==0){
    #pragma unroll
    for (int h=0;h<2;h++){
      mean4[h] = *(const float4*)&g_mean[n0 + lbc + h*128];
      rstd4[h] = *(const float4*)&g_rstd[n0 + lbc + h*128];
    }
  }

  ull acc[8][8];
  #pragma unroll
  for (int i=0;i<8;i++)
    #pragma unroll
    for (int j=0;j<8;j++) acc[i][j] = 0ull;

  const int NS = KDIM/8;
  // prologue: stage 0
  {
    float4 a4 = *(const float4*)(A + (size_t)(m0+lar)*KDIM + lak);
    As[0][lak+0][lar]=a4.x; As[0][lak+1][lar]=a4.y;
    As[0][lak+2][lar]=a4.z; As[0][lak+3][lar]=a4.w;
    float gk=1.f, bk=0.f;
    if (MODE==0){ gk = gg[lbk]; bk = bb[lbk]; }
    #pragma unroll
    for (int h=0;h<2;h++){
      float4 b4 = *(const float4*)(B + (size_t)lbk*S_TOT + n0 + lbc + h*128);
      if (MODE==0){
        b4.x = (b4.x-mean4[h].x)*rstd4[h].x*gk + bk;
        b4.y = (b4.y-mean4[h].y)*rstd4[h].y*gk + bk;
        b4.z = (b4.z-mean4[h].z)*rstd4[h].z*gk + bk;
        b4.w = (b4.w-mean4[h].w)*rstd4[h].w*gk + bk;
      }
      *(float4*)&Bs[0][lbk][lbc + h*128] = b4;
    }
  }
  __syncthreads();
  int st = 0;
  for (int ks=0; ks<NS; ks++){
    float4 a4n; float4 b4n[2];
    bool more = (ks+1 < NS);
    if (more){
      int k0 = (ks+1)*8;
      a4n = *(const float4*)(A + (size_t)(m0+lar)*KDIM + k0 + lak);
      float gk=1.f, bk=0.f;
      if (MODE==0){ gk = gg[k0+lbk]; bk = bb[k0+lbk]; }
      #pragma unroll
      for (int h=0;h<2;h++){
        float4 b4 = *(const float4*)(B + (size_t)(k0+lbk)*S_TOT + n0 + lbc + h*128);
        if (MODE==0){
          b4.x = (b4.x-mean4[h].x)*rstd4[h].x*gk + bk;
          b4.y = (b4.y-mean4[h].y)*rstd4[h].y*gk + bk;
          b4.z = (b4.z-mean4[h].z)*rstd4[h].z*gk + bk;
          b4.w = (b4.w-mean4[h].w)*rstd4[h].w*gk + bk;
        }
        b4n[h] = b4;
      }
    }
    #pragma unroll
    for (int kk=0;kk<8;kk++){
      float4 av0 = *(const float4*)&As[st][kk][ty*8];
      float4 av1 = *(const float4*)&As[st][kk][ty*8+4];
      float a[8] = {av0.x,av0.y,av0.z,av0.w,av1.x,av1.y,av1.z,av1.w};
      ull b2[8];
      #pragma unroll
      for (int c=0;c<4;c++){
        ulonglong2 bp = *(const ulonglong2*)&Bs[st][kk][tx*4 + c*64];
        b2[c*2] = bp.x; b2[c*2+1] = bp.y;
      }
      #pragma unroll
      for (int i=0;i<8;i++){
        ull da = dup2(a[i]);
        #pragma unroll
        for (int j=0;j<8;j++) acc[i][j] = ffma2(da, b2[j], acc[i][j]);
      }
    }
    if (more){
      int ns = st^1;
      As[ns][lak+0][lar]=a4n.x; As[ns][lak+1][lar]=a4n.y;
      As[ns][lak+2][lar]=a4n.z; As[ns][lak+3][lar]=a4n.w;
      *(float4*)&Bs[ns][lbk][lbc]       = b4n[0];
      *(float4*)&Bs[ns][lbk][lbc + 128] = b4n[1];
      __syncthreads();
      st = ns;
    }
  }

  // ---- fused L2-normalization for q,k rows (4 complete heads per m-block) ---
  if (MODE==0 && m0 < 512){
    ull ss2[8];
    #pragma unroll
    for (int j=0;j<8;j++){
      ull s2 = 0ull;
      #pragma unroll
      for (int i=0;i<8;i++) s2 = ffma2(acc[i][j], acc[i][j], s2);
      ss2[j] = s2;
    }
    __syncthreads();   // protect NormS (none needed for As/Bs; cheap safety)
    #pragma unroll
    for (int j=0;j<8;j++){
      int col = tx*4 + (j>>1)*64 + (j&1)*2;
      *(ull*)&NormS[ty][col] = ss2[j];
    }
    __syncthreads();
    int g4 = (ty>>2)*4;
    #pragma unroll
    for (int j=0;j<8;j++){
      int col = tx*4 + (j>>1)*64 + (j&1)*2;
      ull n2 = *(const ull*)&NormS[g4+0][col];
      n2 = fadd2(n2, *(const ull*)&NormS[g4+1][col]);
      n2 = fadd2(n2, *(const ull*)&NormS[g4+2][col]);
      n2 = fadd2(n2, *(const ull*)&NormS[g4+3][col]);
      float2 nf = unpack2(n2);
      float f0 = 1.f/fmaxf(sqrtf(nf.x), 1e-12f);
      float f1 = 1.f/fmaxf(sqrtf(nf.y), 1e-12f);
      ull fv = pack2(f0, f1);
      #pragma unroll
      for (int i=0;i<8;i++) acc[i][j] = fmul2(acc[i][j], fv);
    }
  }

  #pragma unroll
  for (int i=0;i<8;i++){
    int m = m0 + ty*8 + i;
    float bo = (MODE==1) ? bias[m] : 0.f;
    #pragma unroll
    for (int c=0;c<4;c++){
      float2 p0 = unpack2(acc[i][c*2]);
      float2 p1 = unpack2(acc[i][c*2+1]);
      float4 o = make_float4(p0.x+bo, p0.y+bo, p1.x+bo, p1.y+bo);
      *(float4*)(C + (size_t)m*S_TOT + n0 + tx*4 + c*64) = o;
    }
  }
}

// ---------------- 4) probes: q (d,h,w) + k (d), 512 thr ----------------------
// s = m*4096 + i2*512 + t => d=m, h=i2*8+(t>>6), w=t&63
__global__ void k_probes(){
  int bh = blockIdx.x >> 5, c = blockIdx.x & 31;
  int t = threadIdx.x, lane = t & 31;
  const float* qp = g_qkv + (size_t)(bh*32+c)*S_TOT;
  const float* kp = g_qkv + (size_t)(256+bh*32+c)*S_TOT;
  __shared__ float sqd[16], skd[16], sqh[64], sqw[64];
  if (t<64){ sqh[t]=0.f; sqw[t]=0.f; }
  if (t<16){ sqd[t]=0.f; skd[t]=0.f; }
  __syncthreads();
  float qW = 0.f;
  float qH[8];
  #pragma unroll
  for (int i=0;i<8;i++) qH[i]=0.f;
  #pragma unroll 1
  for (int m=0;m<16;m++){
    float qD=0.f, kD=0.f;
    #pragma unroll
    for (int i2=0;i2<8;i2++){
      int s = m*4096 + i2*512 + t;
      float qv = fabsf(qp[s]);
      float kv = fabsf(kp[s]);
      qD += qv; kD += kv; qW += qv; qH[i2] += qv;
    }
    qD = warp_sum(qD); kD = warp_sum(kD);
    if (lane==0){ atomicAdd(&sqd[m], qD); atomicAdd(&skd[m], kD); }
  }
  int hb = t >> 6;
  #pragma unroll
  for (int i2=0;i2<8;i2++){
    float v = warp_sum(qH[i2]);
    if (lane==0) atomicAdd(&sqh[i2*8 + hb], v);
  }
  atomicAdd(&sqw[t & 63], qW);
  __syncthreads();
  if (t<16){ g_qpd[(bh*32+c)*16 + t] = sqd[t]; g_kpd[(bh*32+c)*16 + t] = skd[t]; }
  if (t<64){ g_qph[(bh*32+c)*64 + t] = sqh[t]; g_qpw[(bh*32+c)*64 + t] = sqw[t]; }
}

// ---------------- 5/7/9) score + top-k ---------------------------------------
template<int STAGE>
__global__ void k_score_topk(){
  int bh = blockIdx.x, lane = threadIdx.x;
  const int n  = (STAGE==0)?16:64;
  const int ks = (STAGE==0)?4:8;
  const float* qp = (STAGE==0)?g_qpd:((STAGE==1)?g_qph:g_qpw);
  const float* kp = (STAGE==0)?g_kpd:((STAGE==1)?g_kph:g_kpw);
  int* io = (STAGE==0)?g_idxD:((STAGE==1)?g_idxH:g_idxW);
  __shared__ float sc[64];
  for (int d=0; d<n; d++){
    float v = qp[(bh*32+lane)*n + d] * kp[(bh*32+lane)*n + d];
    v = warp_sum(v);
    if (lane==0) sc[d] = v;
  }
  __syncwarp();
  if (lane==0){
    unsigned long long used = 0ull;
    for (int r=0;r<ks;r++){
      float best=-3.4e38f; int bi=0;
      for (int d=0; d<n; d++){
        if (!((used>>d)&1ull) && sc[d] > best){ best=sc[d]; bi=d; }
      }
      used |= 1ull<<bi;
      io[bh*ks + r] = bi;
    }
  }
}

// ---------------- 6) k probe over h for d in idxD, 512 thr -------------------
__global__ void k_kprobe_h(){
  int bh = blockIdx.x>>5, c = blockIdx.x&31;
  int t = threadIdx.x, lane = t&31;
  const float* kp = g_qkv + (size_t)(256+bh*32+c)*S_TOT;
  __shared__ float sh[64];
  __shared__ int sd[4];
  if (t<64) sh[t]=0.f;
  if (t<4)  sd[t]=g_idxD[bh*4+t];
  __syncthreads();
  float acc[8];
  #pragma unroll
  for (int i=0;i<8;i++) acc[i]=0.f;
  #pragma unroll 1
  for (int di=0; di<4; di++){
    int d = sd[di];
    #pragma unroll
    for (int i2=0;i2<8;i2++){
      int s = d*4096 + i2*512 + t;
      acc[i2] += fabsf(kp[s]);
    }
  }
  int hb = t>>6;
  #pragma unroll
  for (int i2=0;i2<8;i2++){
    float v = warp_sum(acc[i2]);
    if (lane==0) atomicAdd(&sh[i2*8+hb], v);
  }
  __syncthreads();
  if (t<64) g_kph[(bh*32+c)*64+t] = sh[t];
}

// ---------------- 8) k probe over w ------------------------------------------
__global__ void k_kprobe_w(){
  int bh = blockIdx.x>>5, c = blockIdx.x&31;
  int t = threadIdx.x;
  const float* kp = g_qkv + (size_t)(256+bh*32+c)*S_TOT;
  __shared__ float sw[64];
  __shared__ int sd[4], shh[8];
  if (t<64) sw[t]=0.f;
  if (t<4)  sd[t]=g_idxD[bh*4+t];
  if (t<8)  shh[t]=g_idxH[bh*8+t];
  __syncthreads();
  float acc = 0.f;
  int r = t>>6, w = t&63;
  #pragma unroll
  for (int it=0; it<8; it++){
    int combo = r + it*4;
    int di = combo>>3, hi = combo&7;
    int s = sd[di]*4096 + shh[hi]*64 + w;
    acc += fabsf(kp[s]);
  }
  atomicAdd(&sw[w], acc);
  __syncthreads();
  if (t<64) g_kpw[(bh*32+c)*64+t] = sw[t];
}

// ---------------- 10) gather pruned K/V --------------------------------------
__global__ void k_gather(){
  int bh = blockIdx.y;
  int t = threadIdx.x;
  int j = blockIdx.x*8 + (t>>5);
  int c = t & 31;
  int di = j>>6, hi = (j>>3)&7, wi = j&7;
  int s = g_idxD[bh*4+di]*4096 + g_idxH[bh*8+hi]*64 + g_idxW[bh*8+wi];
  g_kf[(bh*256+j)*32 + c] = g_qkv[(size_t)(256+bh*32+c)*S_TOT + s];
  g_vf[(bh*256+j)*32 + c] = g_qkv[(size_t)(512+bh*32+c)*S_TOT + s];
}

// ---------------- 11) attention: 2 queries/thread, f32x2 ---------------------
__global__ void __launch_bounds__(256) k_attn(){
  extern __shared__ float smem[];
  float* sk = smem;            // 256*32
  float* sv = smem + 8192;     // 256*32
  int bh = blockIdx.y, t = threadIdx.x;
  const float4* kf4 = (const float4*)(g_kf + (size_t)bh*8192);
  const float4* vf4 = (const float4*)(g_vf + (size_t)bh*8192);
  #pragma unroll
  for (int i=0;i<8;i++){
    ((float4*)sk)[t + i*256] = kf4[t + i*256];
    ((float4*)sv)[t + i*256] = vf4[t + i*256];
  }
  __syncthreads();
  int s0 = blockIdx.x*512 + t;
  int s1 = s0 + 256;
  ull q0[16], q1[16];
  #pragma unroll
  for (int c=0;c<16;c++){
    const float* p = g_qkv + (size_t)(bh*32 + 2*c)*S_TOT;
    q0[c] = pack2(p[s0], p[S_TOT + s0]);
    q1[c] = pack2(p[s1], p[S_TOT + s1]);
  }
  ull o0[16], o1[16];
  #pragma unroll
  for (int c=0;c<16;c++){ o0[c]=0ull; o1[c]=0ull; }
  float l0=0.f, l1=0.f;
  #pragma unroll 2
  for (int j=0;j<256;j++){
    const ulonglong2* kp = (const ulonglong2*)(sk + j*32);
    ull sA0=0ull,sA1=0ull,sB0=0ull,sB1=0ull;
    #pragma unroll
    for (int u=0;u<8;u++){
      ulonglong2 x = kp[u];
      sA0 = ffma2(q0[2*u],   x.x, sA0);
      sA1 = ffma2(q0[2*u+1], x.y, sA1);
      sB0 = ffma2(q1[2*u],   x.x, sB0);
      sB1 = ffma2(q1[2*u+1], x.y, sB1);
    }
    float2 fa = unpack2(fadd2(sA0,sA1));
    float2 fb = unpack2(fadd2(sB0,sB1));
    float p0 = __expf(fa.x + fa.y);
    float p1 = __expf(fb.x + fb.y);
    l0 += p0; l1 += p1;
    ull pd0 = dup2(p0), pd1 = dup2(p1);
    const ulonglong2* vp = (const ulonglong2*)(sv + j*32);
    #pragma unroll
    for (int u=0;u<8;u++){
      ulonglong2 x = vp[u];
      o0[2*u]   = ffma2(pd0, x.x, o0[2*u]);
      o0[2*u+1] = ffma2(pd0, x.y, o0[2*u+1]);
      o1[2*u]   = ffma2(pd1, x.x, o1[2*u]);
      o1[2*u+1] = ffma2(pd1, x.y, o1[2*u+1]);
    }
  }
  ull d0 = dup2(1.f/l0), d1 = dup2(1.f/l1);
  float4* ob0 = (float4*)(g_aout + ((size_t)bh*S_TOT + (size_t)s0)*32u);
  float4* ob1 = (float4*)(g_aout + ((size_t)bh*S_TOT + (size_t)s1)*32u);
  #pragma unroll
  for (int u=0;u<8;u++){
    float2 a = unpack2(fmul2(o0[2*u], d0));
    float2 b = unpack2(fmul2(o0[2*u+1], d0));
    ob0[u] = make_float4(a.x, a.y, b.x, b.y);
  }
  #pragma unroll
  for (int u=0;u<8;u++){
    float2 a = unpack2(fmul2(o1[2*u], d1));
    float2 b = unpack2(fmul2(o1[2*u+1], d1));
    ob1[u] = make_float4(a.x, a.y, b.x, b.y);
  }
}

// ---------------- host ------------------------------------------------------
extern "C" void kernel_launch(void* const* d_in, const int* in_sizes, int n_in,
                              void* d_out, int out_size) {
  (void)in_sizes; (void)n_in; (void)out_size;
  const float* x     = (const float*)d_in[0];
  const float* g     = (const float*)d_in[1];
  const float* b     = (const float*)d_in[2];
  const float* wqkv  = (const float*)d_in[3];
  const float* wout  = (const float*)d_in[4];
  const float* bout  = (const float*)d_in[5];
  float* out = (float*)d_out;

  k_ln_stats<<<S_TOT/256, 256>>>(x);
  k_gemm<128,0><<<dim3(S_TOT/256, 6), 256>>>(wqkv, x, nullptr, g, b, nullptr);
  k_probes<<<256, 512>>>();
  k_score_topk<0><<<8, 32>>>();
  k_kprobe_h<<<256, 512>>>();
  k_score_topk<1><<<8, 32>>>();
  k_kprobe_w<<<256, 256>>>();
  k_score_topk<2><<<8, 32>>>();
  k_gather<<<dim3(32, 8), 256>>>();
  cudaFuncSetAttribute((const void*)k_attn,
                       cudaFuncAttributeMaxDynamicSharedMemorySize, 65536);
  k_attn<<<dim3(S_TOT/512, 8), 256, 65536>>>();
  k_gemm<256,1><<<dim3(S_TOT/256, 1), 256>>>(wout, nullptr, out, nullptr, nullptr, bout);
}